// round 11
// baseline (speedup 1.0000x reference)
#include <cuda_runtime.h>

// Problem constants (static per init_kwargs)
#define N_IMG 8
#define CIN   64
#define H     112
#define W     112
#define HW    (H * W)        // 12544 patches per image (stride 1, pad 1)
#define DPAT  576            // Cin * K * K
#define COUT  64
#define MEM   1025           // memo table size

// Tiling for the fused csum+bins kernel
#define TILE  16
#define HALO  18             // TILE + 2
#define NHALO (HALO * HALO)  // 324
#define TPI   7              // tiles per image dim (112/16)

// Scratch (device globals — no allocation allowed).
// g_first holds ENCODED first-patch: enc = HW - p (so 0 == "empty bin").
// Zero-initialized at module load; k_scatter re-zeros it each replay, so the
// graph is self-restoring with no dedicated init kernel.
__device__ int   g_bins[N_IMG * HW];
__device__ int   g_first[N_IMG * MEM];
__device__ float g_rep[N_IMG * MEM * COUT];

// ---------------------------------------------------------------------------
// Kernel 1 (fused): per-pixel 64-channel sum (fp32, 8 independent chains)
// into an 18x18 SMEM halo tile, then 3x3 box sum -> quantized summary -> bin.
// If the quantized value q lands within 1e-3 of a truncation boundary
// (integer), the patch sum is recomputed in double (exact to ~1e-13) so the
// bin decision matches the reference's fp32 value except with probability
// ~0 (XLA's own sum error would have to cross the same boundary).
// Final fp32 quantize ops replicate the reference bit-exactly:
//   mean = f32(sum) / 576.0f ; q = mean * 100.0f ; summ = trunc_to_int(q)
// ---------------------------------------------------------------------------
__global__ void k_fused(const float* __restrict__ fmap) {
    __shared__ float sh[NHALO];

    int blk = blockIdx.x;
    int n   = blk / (TPI * TPI);
    int t   = blk - n * (TPI * TPI);
    int ty  = t / TPI, tx = t - (t / TPI) * TPI;
    int gy0 = ty * TILE - 1;     // halo origin (can be -1)
    int gx0 = tx * TILE - 1;

    const float* fb = fmap + n * CIN * HW;

    // Phase 1: fp32 channel sums for halo pixels (OOB -> 0 == zero-pad).
    for (int h = threadIdx.x; h < NHALO; h += blockDim.x) {
        int hy = h / HALO;
        int hx = h - hy * HALO;
        int gy = gy0 + hy;
        int gx = gx0 + hx;
        float s = 0.0f;
        if ((unsigned)gy < H && (unsigned)gx < W) {
            const float* p = fb + gy * W + gx;
            float a0 = 0.f, a1 = 0.f, a2 = 0.f, a3 = 0.f;
            float a4 = 0.f, a5 = 0.f, a6 = 0.f, a7 = 0.f;
#pragma unroll
            for (int c = 0; c < CIN; c += 8) {
                a0 += __ldg(p + (c + 0) * HW);
                a1 += __ldg(p + (c + 1) * HW);
                a2 += __ldg(p + (c + 2) * HW);
                a3 += __ldg(p + (c + 3) * HW);
                a4 += __ldg(p + (c + 4) * HW);
                a5 += __ldg(p + (c + 5) * HW);
                a6 += __ldg(p + (c + 6) * HW);
                a7 += __ldg(p + (c + 7) * HW);
            }
            s = ((a0 + a1) + (a2 + a3)) + ((a4 + a5) + (a6 + a7));
        }
        sh[h] = s;
    }
    __syncthreads();

    // Phase 2: 3x3 box sum, quantize (with double fallback near boundaries),
    // bin, scatter first-occurrence.
    int ly = threadIdx.x / TILE;
    int lx = threadIdx.x - ly * TILE;
    int gy = ty * TILE + ly;
    int gx = tx * TILE + lx;

    float s = 0.0f;
#pragma unroll
    for (int dy = 0; dy < 3; ++dy)
#pragma unroll
        for (int dx = 0; dx < 3; ++dx)
            s += sh[(ly + dy) * HALO + (lx + dx)];

    float sf = s;
    float q  = __fmul_rn(__fdiv_rn(sf, 576.0f), 100.0f);

    // Near a truncation boundary? Recompute the 576-element sum in double.
    // Expected to trigger for only a handful of patches in the whole grid.
    if (fabsf(q - rintf(q)) < 1e-3f) {
        double ds = 0.0;
        for (int c = 0; c < CIN; ++c) {
            const float* pc = fb + c * HW;
            for (int dy = -1; dy <= 1; ++dy) {
                int yy = gy + dy;
                if ((unsigned)yy >= H) continue;
                for (int dx = -1; dx <= 1; ++dx) {
                    int xx = gx + dx;
                    if ((unsigned)xx >= W) continue;
                    ds += (double)pc[yy * W + xx];
                }
            }
        }
        sf = (float)ds;
        q  = __fmul_rn(__fdiv_rn(sf, 576.0f), 100.0f);
    }

    int summ = __float2int_rz(q);            // trunc toward zero == astype(int32)
    int bin  = summ + 512;                   // summ - MIN_SUMMARY
    bin = bin < 0 ? 0 : (bin > MEM - 1 ? MEM - 1 : bin);

    int p = gy * W + gx;
    g_bins[n * HW + p] = bin;
    atomicMax(&g_first[n * MEM + bin], HW - p);   // min-p == max-(HW-p)
}

// ---------------------------------------------------------------------------
// Kernel 2: representative GEMM rows. One 64-thread block per (image, bin).
// Inactive bins (enc==0) exit immediately (~400 of 8200 blocks do work).
// Thread t stages its channel's 3x3 window into SMEM (d = c*9 + kh*3 + kw,
// matching conv_general_dilated_patches order), then computes cout t.
// ---------------------------------------------------------------------------
__global__ void k_rep(const float* __restrict__ fmap,
                      const float* __restrict__ weight,
                      const float* __restrict__ bias) {
    int n = blockIdx.x / MEM;
    int b = blockIdx.x - n * MEM;
    int enc = g_first[n * MEM + b];
    if (enc <= 0) return;                    // empty bin
    int fp = HW - enc;                       // first patch index

    __shared__ float sp[DPAT];
    int t = threadIdx.x;                     // 0..63
    int y = fp / W;
    int x = fp - y * W;

    const float* fb = fmap + (n * CIN + t) * HW;
#pragma unroll
    for (int kh = 0; kh < 3; ++kh) {
        int yy = y + kh - 1;
#pragma unroll
        for (int kw = 0; kw < 3; ++kw) {
            int xx = x + kw - 1;
            float v = 0.0f;
            if (yy >= 0 && yy < H && xx >= 0 && xx < W) v = fb[yy * W + xx];
            sp[t * 9 + kh * 3 + kw] = v;
        }
    }
    __syncthreads();

    const float4* w4 = (const float4*)(weight + t * DPAT);
    const float4* s4 = (const float4*)sp;
    float acc = __ldg(&bias[t]);
#pragma unroll 8
    for (int d = 0; d < DPAT / 4; ++d) {
        float4 wv = __ldg(&w4[d]);
        float4 sv = s4[d];
        acc = fmaf(sv.x, wv.x, acc);
        acc = fmaf(sv.y, wv.y, acc);
        acc = fmaf(sv.z, wv.z, acc);
        acc = fmaf(sv.w, wv.w, acc);
    }
    g_rep[(n * MEM + b) * COUT + t] = acc;
}

// ---------------------------------------------------------------------------
// Kernel 3: broadcast representative rows to NCHW output.
// Thread = (pixel, 16-cout quarter): 4 independent float4 rep loads (L2-hot),
// 16 stores where each warp-STG.32 covers one full 128B line (consecutive
// pixels). Also re-zeros g_first for the next graph replay.
// ---------------------------------------------------------------------------
__global__ void k_scatter(float* __restrict__ out) {
    int tid = threadIdx.x;
    int gid = blockIdx.x * blockDim.x + tid;
    if (gid < N_IMG * MEM) g_first[gid] = 0;   // self-restore for next replay

    int q   = blockIdx.x & 3;                  // cout quarter (16 channels)
    int pix = (blockIdx.x >> 2) * 256 + tid;   // 0 .. N_IMG*HW-1
    int n   = pix / HW;
    int p   = pix - n * HW;
    int bin = g_bins[pix];

    const float4* r4 = (const float4*)(g_rep + (n * MEM + bin) * COUT + q * 16);
    float4 v0 = __ldg(&r4[0]);
    float4 v1 = __ldg(&r4[1]);
    float4 v2 = __ldg(&r4[2]);
    float4 v3 = __ldg(&r4[3]);

    float* ob = out + (n * COUT + q * 16) * HW + p;
    ob[0 * HW]  = v0.x;  ob[1 * HW]  = v0.y;  ob[2 * HW]  = v0.z;  ob[3 * HW]  = v0.w;
    ob[4 * HW]  = v1.x;  ob[5 * HW]  = v1.y;  ob[6 * HW]  = v1.z;  ob[7 * HW]  = v1.w;
    ob[8 * HW]  = v2.x;  ob[9 * HW]  = v2.y;  ob[10 * HW] = v2.z;  ob[11 * HW] = v2.w;
    ob[12 * HW] = v3.x;  ob[13 * HW] = v3.y;  ob[14 * HW] = v3.z;  ob[15 * HW] = v3.w;
}

// ---------------------------------------------------------------------------
extern "C" void kernel_launch(void* const* d_in, const int* in_sizes, int n_in,
                              void* d_out, int out_size) {
    const float* fmap   = (const float*)d_in[0];   // [8,64,112,112]
    const float* weight = (const float*)d_in[1];   // [64,576]
    const float* bias   = (const float*)d_in[2];   // [64]
    float* out = (float*)d_out;                    // [8,64,112,112]
    (void)in_sizes; (void)n_in; (void)out_size;

    k_fused<<<N_IMG * TPI * TPI, 256>>>(fmap);        // 392 blocks
    k_rep<<<N_IMG * MEM, COUT>>>(fmap, weight, bias); // 8200 blocks (~400 active)
    k_scatter<<<(N_IMG * HW / 256) * 4, 256>>>(out);  // 1568 blocks
}

// round 12
// speedup vs baseline: 2.3342x; 2.3342x over previous
#include <cuda_runtime.h>

// Problem constants (static per init_kwargs)
#define N_IMG 8
#define CIN   64
#define H     112
#define W     112
#define HW    (H * W)        // 12544 patches per image (stride 1, pad 1)
#define DPAT  576            // Cin * K * K
#define COUT  64
#define MEM   1025           // memo table size

// Tiling for the fused csum+bins kernel
#define TILE  16
#define HALO  18             // TILE + 2
#define NHALO (HALO * HALO)  // 324
#define TPI   7              // tiles per image dim (112/16)

// Scratch (device globals — no allocation allowed).
// g_first holds ENCODED first-patch: enc = HW - p (so 0 == "empty bin").
// Zero-initialized at module load; k_scatter re-zeros it each replay, so the
// graph is self-restoring with no dedicated init kernel.
__device__ int   g_bins[N_IMG * HW];
__device__ int   g_first[N_IMG * MEM];
__device__ float g_rep[N_IMG * MEM * COUT];

// ---------------------------------------------------------------------------
// Double-single (df64) helpers. All __fadd_rn so fast-math cannot contract
// or reassociate them. Result (hi, lo) satisfies hi + lo == exact to ~2^-48.
// ---------------------------------------------------------------------------
__device__ __forceinline__ void two_sum(float a, float b, float& s, float& e) {
    s = __fadd_rn(a, b);
    float bb   = __fadd_rn(s, -a);
    float err1 = __fadd_rn(a, -__fadd_rn(s, -bb));
    float err2 = __fadd_rn(b, -bb);
    e = __fadd_rn(err1, err2);
}

// (rh, rl) = (ah, al) + (bh, bl), renormalized
__device__ __forceinline__ void df_add(float ah, float al, float bh, float bl,
                                       float& rh, float& rl) {
    float s, e;
    two_sum(ah, bh, s, e);
    e  = __fadd_rn(e, __fadd_rn(al, bl));
    rh = __fadd_rn(s, e);
    rl = __fadd_rn(e, __fadd_rn(s, -rh));
}

// accumulate plain float x into (hi, lo)
__device__ __forceinline__ void df_acc(float& hi, float& lo, float x) {
    float s, e;
    two_sum(hi, x, s, e);
    lo = __fadd_rn(lo, e);
    hi = s;
}

// ---------------------------------------------------------------------------
// Kernel 1 (fused): per-pixel 64-channel sum as df64 (4 chains, 16-wide load
// batches for MLP) into an 18x18 SMEM halo tile, then df64 3x3 box sum ->
// quantized summary -> bin. df64 reproduces the exact sum to ~1e-13, i.e. the
// same bins as the FP64 version that passed, at fp32-pipe cost, branch-free.
// Final fp32 quantize ops replicate the reference bit-exactly:
//   mean = f32(sum) / 576.0f ; q = mean * 100.0f ; summ = trunc_to_int(q)
// ---------------------------------------------------------------------------
__global__ void __launch_bounds__(256, 2) k_fused(const float* __restrict__ fmap) {
    __shared__ float sh_hi[NHALO];
    __shared__ float sh_lo[NHALO];

    int blk = blockIdx.x;
    int n   = blk / (TPI * TPI);
    int t   = blk - n * (TPI * TPI);
    int ty  = t / TPI, tx = t - (t / TPI) * TPI;
    int gy0 = ty * TILE - 1;     // halo origin (can be -1)
    int gx0 = tx * TILE - 1;

    const float* fb = fmap + n * CIN * HW;

    // Phase 1: df64 channel sums for halo pixels (OOB -> 0 == zero-pad).
    for (int h = threadIdx.x; h < NHALO; h += blockDim.x) {
        int hy = h / HALO;
        int hx = h - hy * HALO;
        int gy = gy0 + hy;
        int gx = gx0 + hx;
        float h0 = 0.f, l0 = 0.f, h1 = 0.f, l1 = 0.f;
        float h2 = 0.f, l2 = 0.f, h3 = 0.f, l3 = 0.f;
        if ((unsigned)gy < H && (unsigned)gx < W) {
            const float* p = fb + gy * W + gx;
            for (int cg = 0; cg < 4; ++cg) {        // 4 groups of 16 channels
                float v[16];
#pragma unroll
                for (int i = 0; i < 16; ++i)
                    v[i] = __ldg(p + (cg * 16 + i) * HW);   // 16 loads in flight
#pragma unroll
                for (int i = 0; i < 16; i += 4) {
                    df_acc(h0, l0, v[i + 0]);
                    df_acc(h1, l1, v[i + 1]);
                    df_acc(h2, l2, v[i + 2]);
                    df_acc(h3, l3, v[i + 3]);
                }
            }
        }
        // merge the 4 chains
        float ah, al, bh, bl, rh, rl;
        df_add(h0, l0, h1, l1, ah, al);
        df_add(h2, l2, h3, l3, bh, bl);
        df_add(ah, al, bh, bl, rh, rl);
        sh_hi[h] = rh;
        sh_lo[h] = rl;
    }
    __syncthreads();

    // Phase 2: df64 3x3 box sum, quantize, bin, scatter first-occurrence.
    int ly = threadIdx.x / TILE;
    int lx = threadIdx.x - ly * TILE;
    int gy = ty * TILE + ly;
    int gx = tx * TILE + lx;

    float sh = 0.f, sl = 0.f;
#pragma unroll
    for (int dy = 0; dy < 3; ++dy)
#pragma unroll
        for (int dx = 0; dx < 3; ++dx) {
            int idx = (ly + dy) * HALO + (lx + dx);
            float rh, rl;
            df_add(sh, sl, sh_hi[idx], sh_lo[idx], rh, rl);
            sh = rh; sl = rl;
        }

    float sf = sh;                           // fl(exact patch sum)
    float q  = __fmul_rn(__fdiv_rn(sf, 576.0f), 100.0f);
    int summ = __float2int_rz(q);            // trunc toward zero == astype(int32)
    int bin  = summ + 512;                   // summ - MIN_SUMMARY
    bin = bin < 0 ? 0 : (bin > MEM - 1 ? MEM - 1 : bin);

    int p = gy * W + gx;
    g_bins[n * HW + p] = bin;
    atomicMax(&g_first[n * MEM + bin], HW - p);   // min-p == max-(HW-p)
}

// ---------------------------------------------------------------------------
// Kernel 2: representative GEMM rows. One 64-thread block per (image, bin).
// Inactive bins (enc==0) exit immediately (~400 of 8200 blocks do work).
// Thread t stages its channel's 3x3 window into SMEM (d = c*9 + kh*3 + kw,
// matching conv_general_dilated_patches order), then computes cout t.
// ---------------------------------------------------------------------------
__global__ void k_rep(const float* __restrict__ fmap,
                      const float* __restrict__ weight,
                      const float* __restrict__ bias) {
    int n = blockIdx.x / MEM;
    int b = blockIdx.x - n * MEM;
    int enc = g_first[n * MEM + b];
    if (enc <= 0) return;                    // empty bin
    int fp = HW - enc;                       // first patch index

    __shared__ float sp[DPAT];
    int t = threadIdx.x;                     // 0..63
    int y = fp / W;
    int x = fp - y * W;

    const float* fb = fmap + (n * CIN + t) * HW;
#pragma unroll
    for (int kh = 0; kh < 3; ++kh) {
        int yy = y + kh - 1;
#pragma unroll
        for (int kw = 0; kw < 3; ++kw) {
            int xx = x + kw - 1;
            float v = 0.0f;
            if (yy >= 0 && yy < H && xx >= 0 && xx < W) v = fb[yy * W + xx];
            sp[t * 9 + kh * 3 + kw] = v;
        }
    }
    __syncthreads();

    const float4* w4 = (const float4*)(weight + t * DPAT);
    const float4* s4 = (const float4*)sp;
    float acc = __ldg(&bias[t]);
#pragma unroll 8
    for (int d = 0; d < DPAT / 4; ++d) {
        float4 wv = __ldg(&w4[d]);
        float4 sv = s4[d];
        acc = fmaf(sv.x, wv.x, acc);
        acc = fmaf(sv.y, wv.y, acc);
        acc = fmaf(sv.z, wv.z, acc);
        acc = fmaf(sv.w, wv.w, acc);
    }
    g_rep[(n * MEM + b) * COUT + t] = acc;
}

// ---------------------------------------------------------------------------
// Kernel 3: broadcast representative rows to NCHW output.
// Thread = (pixel, 16-cout quarter): 4 independent float4 rep loads (L2-hot),
// 16 stores where each warp-STG.32 covers one full 128B line (consecutive
// pixels). Also re-zeros g_first for the next graph replay.
// ---------------------------------------------------------------------------
__global__ void k_scatter(float* __restrict__ out) {
    int tid = threadIdx.x;
    int gid = blockIdx.x * blockDim.x + tid;
    if (gid < N_IMG * MEM) g_first[gid] = 0;   // self-restore for next replay

    int q   = blockIdx.x & 3;                  // cout quarter (16 channels)
    int pix = (blockIdx.x >> 2) * 256 + tid;   // 0 .. N_IMG*HW-1
    int n   = pix / HW;
    int p   = pix - n * HW;
    int bin = g_bins[pix];

    const float4* r4 = (const float4*)(g_rep + (n * MEM + bin) * COUT + q * 16);
    float4 v0 = __ldg(&r4[0]);
    float4 v1 = __ldg(&r4[1]);
    float4 v2 = __ldg(&r4[2]);
    float4 v3 = __ldg(&r4[3]);

    float* ob = out + (n * COUT + q * 16) * HW + p;
    ob[0 * HW]  = v0.x;  ob[1 * HW]  = v0.y;  ob[2 * HW]  = v0.z;  ob[3 * HW]  = v0.w;
    ob[4 * HW]  = v1.x;  ob[5 * HW]  = v1.y;  ob[6 * HW]  = v1.z;  ob[7 * HW]  = v1.w;
    ob[8 * HW]  = v2.x;  ob[9 * HW]  = v2.y;  ob[10 * HW] = v2.z;  ob[11 * HW] = v2.w;
    ob[12 * HW] = v3.x;  ob[13 * HW] = v3.y;  ob[14 * HW] = v3.z;  ob[15 * HW] = v3.w;
}

// ---------------------------------------------------------------------------
extern "C" void kernel_launch(void* const* d_in, const int* in_sizes, int n_in,
                              void* d_out, int out_size) {
    const float* fmap   = (const float*)d_in[0];   // [8,64,112,112]
    const float* weight = (const float*)d_in[1];   // [64,576]
    const float* bias   = (const float*)d_in[2];   // [64]
    float* out = (float*)d_out;                    // [8,64,112,112]
    (void)in_sizes; (void)n_in; (void)out_size;

    k_fused<<<N_IMG * TPI * TPI, 256>>>(fmap);        // 392 blocks
    k_rep<<<N_IMG * MEM, COUT>>>(fmap, weight, bias); // 8200 blocks (~400 active)
    k_scatter<<<(N_IMG * HW / 256) * 4, 256>>>(out);  // 1568 blocks
}